// round 10
// baseline (speedup 1.0000x reference)
#include <cuda_runtime.h>
#include <cuda_fp16.h>
#include <cstdint>

#define N_NODES 100000
#define N_FEAT  512
#define N_EDGES 3200000
#define NCH16   (N_FEAT / 8)   // 64 uint4 (8-half) chunks per row

// Scratch (allocation-free rule: __device__ globals)
__device__ __half g_wh[(size_t)N_FEAT * N_FEAT];   // W in fp16
__device__ __half g_xw[(size_t)N_NODES * N_FEAT];  // X @ W in fp16
__device__ float g_dinv[N_NODES];                  // rsqrt(deg+1)
__device__ int   g_deg[N_NODES];                   // in-degree (no self loop)
__device__ int   g_off[N_NODES];                   // CSR chunk start
__device__ int   g_cursor[N_NODES];                // fill cursor
__device__ int   g_csr_src[N_EDGES];               // src ids grouped by dst
__device__ float g_csr_norm[N_EDGES];              // dinv[src]*dinv[dst]
__device__ int   g_total;                          // chunk allocator

// ---------------------------------------------------------------------------
// fp32 -> fp16 helpers
// ---------------------------------------------------------------------------
__device__ __forceinline__ uint4 cvt8(const float4 a, const float4 b) {
    __half2 h0 = __floats2half2_rn(a.x, a.y);
    __half2 h1 = __floats2half2_rn(a.z, a.w);
    __half2 h2 = __floats2half2_rn(b.x, b.y);
    __half2 h3 = __floats2half2_rn(b.z, b.w);
    uint4 v;
    v.x = *reinterpret_cast<unsigned*>(&h0);
    v.y = *reinterpret_cast<unsigned*>(&h1);
    v.z = *reinterpret_cast<unsigned*>(&h2);
    v.w = *reinterpret_cast<unsigned*>(&h3);
    return v;
}

__global__ void cvtW_kernel(const float* __restrict__ W) {
    int i = blockIdx.x * blockDim.x + threadIdx.x;   // over 512*512/8
    if (i < N_FEAT * N_FEAT / 8) {
        const float4* s = reinterpret_cast<const float4*>(W) + 2 * (size_t)i;
        reinterpret_cast<uint4*>(g_wh)[i] = cvt8(s[0], s[1]);
    }
}

// ---------------------------------------------------------------------------
// CSR build
// ---------------------------------------------------------------------------
__global__ void zero_kernel() {
    int i = blockIdx.x * blockDim.x + threadIdx.x;
    if (i < N_NODES) g_deg[i] = 0;
    if (i == 0) g_total = 0;
}

__global__ void count_deg_kernel(const int* __restrict__ dst) {
    int e = blockIdx.x * blockDim.x + threadIdx.x;
    if (e < N_EDGES) atomicAdd(&g_deg[dst[e]], 1);
}

__global__ void alloc_kernel() {
    int i = blockIdx.x * blockDim.x + threadIdx.x;
    if (i < N_NODES) {
        int d = g_deg[i];
        int o = atomicAdd(&g_total, d);   // disjoint contiguous ranges
        g_off[i] = o;
        g_cursor[i] = o;
        g_dinv[i] = rsqrtf((float)d + 1.0f);  // +1 = self loop
    }
}

__global__ void fill_kernel(const int* __restrict__ ei) {
    int e = blockIdx.x * blockDim.x + threadIdx.x;
    if (e < N_EDGES) {
        int s = ei[e];
        int d = ei[N_EDGES + e];
        int pos = atomicAdd(&g_cursor[d], 1);
        g_csr_src[pos] = s;
        g_csr_norm[pos] = g_dinv[s] * g_dinv[d];   // dinv ready (fill after alloc)
    }
}

// ---------------------------------------------------------------------------
// GEMM: g_xw = fp16(onehot @ g_wh), fp16 mma m16n8k16 with fp32 accumulate.
// A read directly as fp32 and converted in-register (cvtX fused away).
// 256x128x32 block tile, 256 threads = 8 warps (4m x 2n), warp tile 64x64.
// ---------------------------------------------------------------------------
#define BM 256
#define BN 128
#define BK 32
#define SAH 40    // A smem row stride (halves)
#define SBH 136   // B smem row stride (halves)
#define A_BUF_H (BM * SAH)              // 10240 halves per buffer
#define B_BASE_H (2 * A_BUF_H)          // 20480
#define B_BUF_H (BK * SBH)              // 4352 halves per buffer
#define SMEM_DYN ((B_BASE_H + 2 * B_BUF_H) * 2)  // 58368 bytes

__device__ __forceinline__ unsigned smem_u32(const void* p) {
    return (unsigned)__cvta_generic_to_shared(p);
}

__device__ __forceinline__ void ldsm_x4(unsigned* r, const void* p) {
    asm volatile("ldmatrix.sync.aligned.m8n8.x4.shared.b16 {%0,%1,%2,%3}, [%4];"
                 : "=r"(r[0]), "=r"(r[1]), "=r"(r[2]), "=r"(r[3]) : "r"(smem_u32(p)));
}

__device__ __forceinline__ void ldsm_x4_trans(unsigned* r, const void* p) {
    asm volatile("ldmatrix.sync.aligned.m8n8.x4.trans.shared.b16 {%0,%1,%2,%3}, [%4];"
                 : "=r"(r[0]), "=r"(r[1]), "=r"(r[2]), "=r"(r[3]) : "r"(smem_u32(p)));
}

__device__ __forceinline__ void mma_f16(float* c, const unsigned* a, const unsigned* b) {
    asm volatile(
        "mma.sync.aligned.m16n8k16.row.col.f32.f16.f16.f32 "
        "{%0,%1,%2,%3}, {%4,%5,%6,%7}, {%8,%9}, {%0,%1,%2,%3};"
        : "+f"(c[0]), "+f"(c[1]), "+f"(c[2]), "+f"(c[3])
        : "r"(a[0]), "r"(a[1]), "r"(a[2]), "r"(a[3]), "r"(b[0]), "r"(b[1]));
}

__global__ __launch_bounds__(256, 1) void gemm_kernel(const float* __restrict__ A) {
    extern __shared__ __half sm[];

    const int tid = threadIdx.x;
    const int rowBase = blockIdx.y * BM;
    const int colBase = blockIdx.x * BN;

    // A: 256 rows x 32 fp32, per thread 8 fp32 (2 float4) per row-slice i.
    const int arow = tid >> 2;            // 0..63 (+64*i)
    const int akc  = (tid & 3) * 8;       // 0,8,16,24
    // B: 32 k x 128 n fp16, per thread 8 halves per slice j.
    const int bk   = tid >> 4;            // 0..15 (+16*j)
    const int bn   = (tid & 15) * 8;      // 0..120

    const float*  Aptr = A + (size_t)(rowBase + arow) * N_FEAT + akc;
    const __half* Bptr = g_wh + (size_t)bk * N_FEAT + colBase + bn;

    bool aok[4];
#pragma unroll
    for (int i = 0; i < 4; i++) aok[i] = (rowBase + arow + 64 * i) < N_NODES;

    // Warp tiling: 8 warps as 4(m) x 2(n); warp tile 64x64.
    const int warpId = tid >> 5;
    const int lane = tid & 31;
    const int wm = (warpId >> 1) * 64;    // 0,64,128,192
    const int wn = (warpId & 1) * 64;     // 0,64
    const int lr = lane & 15;             // ldmatrix row
    const int lc = (lane >> 4) * 8;       // ldmatrix col block
    const int qr = lane >> 2;             // mma c row
    const int qc = lane & 3;              // mma c col pair

    float acc[4][8][4] = {};              // [mi][ni][reg]

    float4 aR[4][2];
    uint4 bR[2];
#pragma unroll
    for (int i = 0; i < 4; i++) {
        if (aok[i]) {
            aR[i][0] = *reinterpret_cast<const float4*>(Aptr + (size_t)64 * i * N_FEAT);
            aR[i][1] = *reinterpret_cast<const float4*>(Aptr + (size_t)64 * i * N_FEAT + 4);
        } else {
            aR[i][0] = aR[i][1] = make_float4(0.f, 0.f, 0.f, 0.f);
        }
    }
#pragma unroll
    for (int j = 0; j < 2; j++)
        bR[j] = *reinterpret_cast<const uint4*>(Bptr + (size_t)16 * j * N_FEAT);

    int buf = 0;
    for (int kb = 0; kb < N_FEAT; kb += BK) {
        // store prefetched tile (convert A to fp16 here)
#pragma unroll
        for (int i = 0; i < 4; i++)
            *reinterpret_cast<uint4*>(&sm[buf * A_BUF_H + (arow + 64 * i) * SAH + akc]) =
                cvt8(aR[i][0], aR[i][1]);
#pragma unroll
        for (int j = 0; j < 2; j++)
            *reinterpret_cast<uint4*>(&sm[B_BASE_H + buf * B_BUF_H + (bk + 16 * j) * SBH + bn]) = bR[j];
        __syncthreads();

        // prefetch next tile
        if (kb + BK < N_FEAT) {
#pragma unroll
            for (int i = 0; i < 4; i++)
                if (aok[i]) {
                    aR[i][0] = *reinterpret_cast<const float4*>(
                        Aptr + (size_t)64 * i * N_FEAT + kb + BK);
                    aR[i][1] = *reinterpret_cast<const float4*>(
                        Aptr + (size_t)64 * i * N_FEAT + kb + BK + 4);
                }
#pragma unroll
            for (int j = 0; j < 2; j++)
                bR[j] = *reinterpret_cast<const uint4*>(
                    Bptr + (size_t)(kb + BK + 16 * j) * N_FEAT);
        }

#pragma unroll
        for (int ks = 0; ks < 2; ks++) {
            const int k0 = ks * 16;
            unsigned af[4][4];
#pragma unroll
            for (int mi = 0; mi < 4; mi++)
                ldsm_x4(af[mi], &sm[buf * A_BUF_H + (wm + mi * 16 + lr) * SAH + k0 + lc]);
            unsigned bf[4][4];
#pragma unroll
            for (int nj = 0; nj < 4; nj++)
                ldsm_x4_trans(bf[nj], &sm[B_BASE_H + buf * B_BUF_H + (k0 + lr) * SBH + wn + nj * 16 + lc]);
#pragma unroll
            for (int mi = 0; mi < 4; mi++)
#pragma unroll
                for (int ni = 0; ni < 8; ni++)
                    mma_f16(acc[mi][ni], af[mi], &bf[ni >> 1][(ni & 1) * 2]);
        }
        __syncthreads();
        buf ^= 1;
    }

    // Epilogue: fp16 stores. c0,c1 -> (qr, 2qc..); c2,c3 -> (qr+8, ...)
#pragma unroll
    for (int mi = 0; mi < 4; mi++) {
        const int r0 = rowBase + wm + mi * 16 + qr;
        const int r1 = r0 + 8;
#pragma unroll
        for (int ni = 0; ni < 8; ni++) {
            const int col = colBase + wn + ni * 8 + 2 * qc;
            if (r0 < N_NODES) {
                __half2 h = __floats2half2_rn(acc[mi][ni][0], acc[mi][ni][1]);
                *reinterpret_cast<__half2*>(&g_xw[(size_t)r0 * N_FEAT + col]) = h;
            }
            if (r1 < N_NODES) {
                __half2 h = __floats2half2_rn(acc[mi][ni][2], acc[mi][ni][3]);
                *reinterpret_cast<__half2*>(&g_xw[(size_t)r1 * N_FEAT + col]) = h;
            }
        }
    }
}

// ---------------------------------------------------------------------------
// Fused aggregate + bias + relu + softmax. ONE WARP PER NODE: 32 threads,
// 2 uint4 (16 halves) per thread, softmax entirely via warp shuffles.
// 256-thread blocks hold 8 independent warps (no __syncthreads anywhere).
// ---------------------------------------------------------------------------
__device__ __forceinline__ void acc_half8(float4& a0, float4& a1, uint4 raw, float m) {
    __half2 h0 = *reinterpret_cast<__half2*>(&raw.x);
    __half2 h1 = *reinterpret_cast<__half2*>(&raw.y);
    __half2 h2 = *reinterpret_cast<__half2*>(&raw.z);
    __half2 h3 = *reinterpret_cast<__half2*>(&raw.w);
    float2 f0 = __half22float2(h0);
    float2 f1 = __half22float2(h1);
    float2 f2 = __half22float2(h2);
    float2 f3 = __half22float2(h3);
    a0.x = fmaf(f0.x, m, a0.x); a0.y = fmaf(f0.y, m, a0.y);
    a0.z = fmaf(f1.x, m, a0.z); a0.w = fmaf(f1.y, m, a0.w);
    a1.x = fmaf(f2.x, m, a1.x); a1.y = fmaf(f2.y, m, a1.y);
    a1.z = fmaf(f3.x, m, a1.z); a1.w = fmaf(f3.y, m, a1.w);
}

__global__ __launch_bounds__(256) void aggregate_kernel(const float* __restrict__ bias,
                                                        float* __restrict__ out) {
    const int n = blockIdx.x * 8 + (threadIdx.x >> 5);
    if (n >= N_NODES) return;
    const int lane = threadIdx.x & 31;
    const float dn = g_dinv[n];
    const uint4* __restrict__ xw4 = reinterpret_cast<const uint4*>(g_xw);

    // chunks lane and lane+32 of the 64 uint4 per row
    const size_t rb = (size_t)n * NCH16;
    float4 A0 = make_float4(0.f, 0.f, 0.f, 0.f), A1 = A0;   // chunk lane
    float4 B0 = A0, B1 = A0;                                 // chunk lane+32
    acc_half8(A0, A1, xw4[rb + lane], dn * dn);              // self loop
    acc_half8(B0, B1, xw4[rb + lane + 32], dn * dn);

    const int start = g_off[n];
    const int cnt = g_deg[n];
    const int* __restrict__ lst = g_csr_src + start;
    const float* __restrict__ nrm = g_csr_norm + start;

    int i = 0;
    for (; i + 4 <= cnt; i += 4) {
        int s0 = lst[i], s1 = lst[i + 1], s2 = lst[i + 2], s3 = lst[i + 3];
        float m0 = nrm[i], m1 = nrm[i + 1], m2 = nrm[i + 2], m3 = nrm[i + 3];
        size_t r0 = (size_t)s0 * NCH16, r1 = (size_t)s1 * NCH16;
        size_t r2 = (size_t)s2 * NCH16, r3 = (size_t)s3 * NCH16;
        uint4 va0 = xw4[r0 + lane],      va1 = xw4[r1 + lane];
        uint4 va2 = xw4[r2 + lane],      va3 = xw4[r3 + lane];
        uint4 vb0 = xw4[r0 + lane + 32], vb1 = xw4[r1 + lane + 32];
        uint4 vb2 = xw4[r2 + lane + 32], vb3 = xw4[r3 + lane + 32];
        acc_half8(A0, A1, va0, m0); acc_half8(B0, B1, vb0, m0);
        acc_half8(A0, A1, va1, m1); acc_half8(B0, B1, vb1, m1);
        acc_half8(A0, A1, va2, m2); acc_half8(B0, B1, vb2, m2);
        acc_half8(A0, A1, va3, m3); acc_half8(B0, B1, vb3, m3);
    }
    for (; i < cnt; i++) {
        int s = lst[i];
        float m = nrm[i];
        size_t r = (size_t)s * NCH16;
        acc_half8(A0, A1, xw4[r + lane], m);
        acc_half8(B0, B1, xw4[r + lane + 32], m);
    }

    // bias + relu
    const float4* b4 = reinterpret_cast<const float4*>(bias);
    float4 ba0 = b4[2 * lane], ba1 = b4[2 * lane + 1];
    float4 bb0 = b4[2 * (lane + 32)], bb1 = b4[2 * (lane + 32) + 1];
    A0.x = fmaxf(A0.x + ba0.x, 0.f); A0.y = fmaxf(A0.y + ba0.y, 0.f);
    A0.z = fmaxf(A0.z + ba0.z, 0.f); A0.w = fmaxf(A0.w + ba0.w, 0.f);
    A1.x = fmaxf(A1.x + ba1.x, 0.f); A1.y = fmaxf(A1.y + ba1.y, 0.f);
    A1.z = fmaxf(A1.z + ba1.z, 0.f); A1.w = fmaxf(A1.w + ba1.w, 0.f);
    B0.x = fmaxf(B0.x + bb0.x, 0.f); B0.y = fmaxf(B0.y + bb0.y, 0.f);
    B0.z = fmaxf(B0.z + bb0.z, 0.f); B0.w = fmaxf(B0.w + bb0.w, 0.f);
    B1.x = fmaxf(B1.x + bb1.x, 0.f); B1.y = fmaxf(B1.y + bb1.y, 0.f);
    B1.z = fmaxf(B1.z + bb1.z, 0.f); B1.w = fmaxf(B1.w + bb1.w, 0.f);

    // softmax over 512 = warp shuffles only
    float m = fmaxf(fmaxf(fmaxf(A0.x, A0.y), fmaxf(A0.z, A0.w)),
                    fmaxf(fmaxf(A1.x, A1.y), fmaxf(A1.z, A1.w)));
    m = fmaxf(m, fmaxf(fmaxf(fmaxf(B0.x, B0.y), fmaxf(B0.z, B0.w)),
                       fmaxf(fmaxf(B1.x, B1.y), fmaxf(B1.z, B1.w))));
#pragma unroll
    for (int o = 16; o > 0; o >>= 1)
        m = fmaxf(m, __shfl_xor_sync(0xFFFFFFFF, m, o));

    A0.x = __expf(A0.x - m); A0.y = __expf(A0.y - m);
    A0.z = __expf(A0.z - m); A0.w = __expf(A0.w - m);
    A1.x = __expf(A1.x - m); A1.y = __expf(A1.y - m);
    A1.z = __expf(A1.z - m); A1.w = __expf(A1.w - m);
    B0.x = __expf(B0.x - m); B0.y = __expf(B0.y - m);
    B0.z = __expf(B0.z - m); B0.w = __expf(B0.w - m);
    B1.x = __expf(B1.x - m); B1.y = __expf(B1.y - m);
    B1.z = __expf(B1.z - m); B1.w = __expf(B1.w - m);

    float s = A0.x + A0.y + A0.z + A0.w + A1.x + A1.y + A1.z + A1.w +
              B0.x + B0.y + B0.z + B0.w + B1.x + B1.y + B1.z + B1.w;
#pragma unroll
    for (int o = 16; o > 0; o >>= 1)
        s += __shfl_xor_sync(0xFFFFFFFF, s, o);

    float inv = __frcp_rn(s);
    A0.x *= inv; A0.y *= inv; A0.z *= inv; A0.w *= inv;
    A1.x *= inv; A1.y *= inv; A1.z *= inv; A1.w *= inv;
    B0.x *= inv; B0.y *= inv; B0.z *= inv; B0.w *= inv;
    B1.x *= inv; B1.y *= inv; B1.z *= inv; B1.w *= inv;

    float4* orow = reinterpret_cast<float4*>(out) + (size_t)n * (N_FEAT / 4);
    orow[2 * lane]            = A0;
    orow[2 * lane + 1]        = A1;
    orow[2 * (lane + 32)]     = B0;
    orow[2 * (lane + 32) + 1] = B1;
}

// ---------------------------------------------------------------------------
// Launch. CSR build forked onto a side stream; GEMM kept as 4th submitted
// launch for the ncu slot.
// ---------------------------------------------------------------------------
extern "C" void kernel_launch(void* const* d_in, const int* in_sizes, int n_in,
                              void* d_out, int out_size) {
    const float* onehot = (const float*)d_in[0];
    const int*   ei     = (const int*)d_in[1];    // [2, E]: src then dst
    const float* W      = (const float*)d_in[2];
    const float* b      = (const float*)d_in[3];
    float* out = (float*)d_out;

    static cudaStream_t side = nullptr;
    static cudaEvent_t evFork = nullptr, evJoin = nullptr;
    if (!side) {
        cudaStreamCreateWithFlags(&side, cudaStreamNonBlocking);
        cudaEventCreateWithFlags(&evFork, cudaEventDisableTiming);
        cudaEventCreateWithFlags(&evJoin, cudaEventDisableTiming);
        cudaFuncSetAttribute(gemm_kernel, cudaFuncAttributeMaxDynamicSharedMemorySize, SMEM_DYN);
    }

    // fork: side branch handles the CSR build
    cudaEventRecord(evFork, 0);
    cudaStreamWaitEvent(side, evFork, 0);

    cvtW_kernel<<<(N_FEAT * N_FEAT / 8 + 255) / 256, 256>>>(W);                     // #1
    zero_kernel<<<(N_NODES + 255) / 256, 256, 0, side>>>();                         // #2
    count_deg_kernel<<<(N_EDGES + 255) / 256, 256, 0, side>>>(ei + N_EDGES);        // #3
    gemm_kernel<<<dim3(N_FEAT / BN, (N_NODES + BM - 1) / BM), 256, SMEM_DYN>>>(onehot); // #4
    alloc_kernel<<<(N_NODES + 255) / 256, 256, 0, side>>>();
    fill_kernel<<<(N_EDGES + 255) / 256, 256, 0, side>>>(ei);

    // join: aggregate needs both the GEMM (main) and the CSR (side)
    cudaEventRecord(evJoin, side);
    cudaStreamWaitEvent(0, evJoin, 0);

    aggregate_kernel<<<(N_NODES + 7) / 8, 256>>>(b, out);
}

// round 11
// speedup vs baseline: 1.0098x; 1.0098x over previous
#include <cuda_runtime.h>
#include <cuda_fp16.h>
#include <cstdint>

#define N_NODES 100000
#define N_FEAT  512
#define N_EDGES 3200000
#define NCH16   (N_FEAT / 8)   // 64 uint4 (8-half) chunks per row

// Scratch (allocation-free rule: __device__ globals)
__device__ __half g_wh[(size_t)N_FEAT * N_FEAT];   // W in fp16
__device__ __half g_xw[(size_t)N_NODES * N_FEAT];  // X @ W in fp16
__device__ float g_dinv[N_NODES];                  // rsqrt(deg+1)
__device__ int   g_deg[N_NODES];                   // in-degree (no self loop)
__device__ int   g_off[N_NODES];                   // CSR chunk start
__device__ int   g_cursor[N_NODES];                // fill cursor
__device__ int   g_csr_src[N_EDGES];               // src ids grouped by dst
__device__ float g_csr_norm[N_EDGES];              // dinv[src]*dinv[dst]
__device__ int   g_total;                          // chunk allocator

// ---------------------------------------------------------------------------
// fp32 -> fp16 helpers
// ---------------------------------------------------------------------------
__device__ __forceinline__ uint4 cvt8(const float4 a, const float4 b) {
    __half2 h0 = __floats2half2_rn(a.x, a.y);
    __half2 h1 = __floats2half2_rn(a.z, a.w);
    __half2 h2 = __floats2half2_rn(b.x, b.y);
    __half2 h3 = __floats2half2_rn(b.z, b.w);
    uint4 v;
    v.x = *reinterpret_cast<unsigned*>(&h0);
    v.y = *reinterpret_cast<unsigned*>(&h1);
    v.z = *reinterpret_cast<unsigned*>(&h2);
    v.w = *reinterpret_cast<unsigned*>(&h3);
    return v;
}

__global__ void cvtW_kernel(const float* __restrict__ W) {
    int i = blockIdx.x * blockDim.x + threadIdx.x;   // over 512*512/8
    if (i < N_FEAT * N_FEAT / 8) {
        const float4* s = reinterpret_cast<const float4*>(W) + 2 * (size_t)i;
        reinterpret_cast<uint4*>(g_wh)[i] = cvt8(s[0], s[1]);
    }
}

// ---------------------------------------------------------------------------
// CSR build
// ---------------------------------------------------------------------------
__global__ void zero_kernel() {
    int i = blockIdx.x * blockDim.x + threadIdx.x;
    if (i < N_NODES) g_deg[i] = 0;
    if (i == 0) g_total = 0;
}

__global__ void count_deg_kernel(const int* __restrict__ dst) {
    int e = blockIdx.x * blockDim.x + threadIdx.x;
    if (e < N_EDGES) atomicAdd(&g_deg[__ldcs(dst + e)], 1);
}

__global__ void alloc_kernel() {
    int i = blockIdx.x * blockDim.x + threadIdx.x;
    if (i < N_NODES) {
        int d = g_deg[i];
        int o = atomicAdd(&g_total, d);   // disjoint contiguous ranges
        g_off[i] = o;
        g_cursor[i] = o;
        g_dinv[i] = rsqrtf((float)d + 1.0f);  // +1 = self loop
    }
}

__global__ void fill_kernel(const int* __restrict__ ei) {
    int e = blockIdx.x * blockDim.x + threadIdx.x;
    if (e < N_EDGES) {
        int s = __ldcs(ei + e);
        int d = __ldcs(ei + N_EDGES + e);
        int pos = atomicAdd(&g_cursor[d], 1);
        g_csr_src[pos] = s;
        g_csr_norm[pos] = g_dinv[s] * g_dinv[d];   // dinv ready (fill after alloc)
    }
}

// ---------------------------------------------------------------------------
// GEMM: g_xw = fp16(onehot @ g_wh), fp16 mma m16n8k16 with fp32 accumulate.
// A read as fp32 with streaming hint (read once), converted in-register.
// 256x128x32 block tile, 256 threads = 8 warps (4m x 2n), warp tile 64x64.
// ---------------------------------------------------------------------------
#define BM 256
#define BN 128
#define BK 32
#define SAH 40    // A smem row stride (halves)
#define SBH 136   // B smem row stride (halves)
#define A_BUF_H (BM * SAH)              // 10240 halves per buffer
#define B_BASE_H (2 * A_BUF_H)          // 20480
#define B_BUF_H (BK * SBH)              // 4352 halves per buffer
#define SMEM_DYN ((B_BASE_H + 2 * B_BUF_H) * 2)  // 58368 bytes

__device__ __forceinline__ unsigned smem_u32(const void* p) {
    return (unsigned)__cvta_generic_to_shared(p);
}

__device__ __forceinline__ void ldsm_x4(unsigned* r, const void* p) {
    asm volatile("ldmatrix.sync.aligned.m8n8.x4.shared.b16 {%0,%1,%2,%3}, [%4];"
                 : "=r"(r[0]), "=r"(r[1]), "=r"(r[2]), "=r"(r[3]) : "r"(smem_u32(p)));
}

__device__ __forceinline__ void ldsm_x4_trans(unsigned* r, const void* p) {
    asm volatile("ldmatrix.sync.aligned.m8n8.x4.trans.shared.b16 {%0,%1,%2,%3}, [%4];"
                 : "=r"(r[0]), "=r"(r[1]), "=r"(r[2]), "=r"(r[3]) : "r"(smem_u32(p)));
}

__device__ __forceinline__ void mma_f16(float* c, const unsigned* a, const unsigned* b) {
    asm volatile(
        "mma.sync.aligned.m16n8k16.row.col.f32.f16.f16.f32 "
        "{%0,%1,%2,%3}, {%4,%5,%6,%7}, {%8,%9}, {%0,%1,%2,%3};"
        : "+f"(c[0]), "+f"(c[1]), "+f"(c[2]), "+f"(c[3])
        : "r"(a[0]), "r"(a[1]), "r"(a[2]), "r"(a[3]), "r"(b[0]), "r"(b[1]));
}

__global__ __launch_bounds__(256, 1) void gemm_kernel(const float* __restrict__ A) {
    extern __shared__ __half sm[];

    const int tid = threadIdx.x;
    const int rowBase = blockIdx.y * BM;
    const int colBase = blockIdx.x * BN;

    // A: 256 rows x 32 fp32, per thread 8 fp32 (2 float4) per row-slice i.
    const int arow = tid >> 2;            // 0..63 (+64*i)
    const int akc  = (tid & 3) * 8;       // 0,8,16,24
    // B: 32 k x 128 n fp16, per thread 8 halves per slice j.
    const int bk   = tid >> 4;            // 0..15 (+16*j)
    const int bn   = (tid & 15) * 8;      // 0..120

    const float*  Aptr = A + (size_t)(rowBase + arow) * N_FEAT + akc;
    const __half* Bptr = g_wh + (size_t)bk * N_FEAT + colBase + bn;

    bool aok[4];
#pragma unroll
    for (int i = 0; i < 4; i++) aok[i] = (rowBase + arow + 64 * i) < N_NODES;

    // Warp tiling: 8 warps as 4(m) x 2(n); warp tile 64x64.
    const int warpId = tid >> 5;
    const int lane = tid & 31;
    const int wm = (warpId >> 1) * 64;    // 0,64,128,192
    const int wn = (warpId & 1) * 64;     // 0,64
    const int lr = lane & 15;             // ldmatrix row
    const int lc = (lane >> 4) * 8;       // ldmatrix col block
    const int qr = lane >> 2;             // mma c row
    const int qc = lane & 3;              // mma c col pair

    float acc[4][8][4] = {};              // [mi][ni][reg]

    float4 aR[4][2];
    uint4 bR[2];
#pragma unroll
    for (int i = 0; i < 4; i++) {
        if (aok[i]) {
            aR[i][0] = __ldcs(reinterpret_cast<const float4*>(Aptr + (size_t)64 * i * N_FEAT));
            aR[i][1] = __ldcs(reinterpret_cast<const float4*>(Aptr + (size_t)64 * i * N_FEAT + 4));
        } else {
            aR[i][0] = aR[i][1] = make_float4(0.f, 0.f, 0.f, 0.f);
        }
    }
#pragma unroll
    for (int j = 0; j < 2; j++)
        bR[j] = *reinterpret_cast<const uint4*>(Bptr + (size_t)16 * j * N_FEAT);

    int buf = 0;
    for (int kb = 0; kb < N_FEAT; kb += BK) {
        // store prefetched tile (convert A to fp16 here)
#pragma unroll
        for (int i = 0; i < 4; i++)
            *reinterpret_cast<uint4*>(&sm[buf * A_BUF_H + (arow + 64 * i) * SAH + akc]) =
                cvt8(aR[i][0], aR[i][1]);
#pragma unroll
        for (int j = 0; j < 2; j++)
            *reinterpret_cast<uint4*>(&sm[B_BASE_H + buf * B_BUF_H + (bk + 16 * j) * SBH + bn]) = bR[j];
        __syncthreads();

        // prefetch next tile
        if (kb + BK < N_FEAT) {
#pragma unroll
            for (int i = 0; i < 4; i++)
                if (aok[i]) {
                    aR[i][0] = __ldcs(reinterpret_cast<const float4*>(
                        Aptr + (size_t)64 * i * N_FEAT + kb + BK));
                    aR[i][1] = __ldcs(reinterpret_cast<const float4*>(
                        Aptr + (size_t)64 * i * N_FEAT + kb + BK + 4));
                }
#pragma unroll
            for (int j = 0; j < 2; j++)
                bR[j] = *reinterpret_cast<const uint4*>(
                    Bptr + (size_t)(kb + BK + 16 * j) * N_FEAT);
        }

#pragma unroll
        for (int ks = 0; ks < 2; ks++) {
            const int k0 = ks * 16;
            unsigned af[4][4];
#pragma unroll
            for (int mi = 0; mi < 4; mi++)
                ldsm_x4(af[mi], &sm[buf * A_BUF_H + (wm + mi * 16 + lr) * SAH + k0 + lc]);
            unsigned bf[4][4];
#pragma unroll
            for (int nj = 0; nj < 4; nj++)
                ldsm_x4_trans(bf[nj], &sm[B_BASE_H + buf * B_BUF_H + (k0 + lr) * SBH + wn + nj * 16 + lc]);
#pragma unroll
            for (int mi = 0; mi < 4; mi++)
#pragma unroll
                for (int ni = 0; ni < 8; ni++)
                    mma_f16(acc[mi][ni], af[mi], &bf[ni >> 1][(ni & 1) * 2]);
        }
        __syncthreads();
        buf ^= 1;
    }

    // Epilogue: fp16 stores. c0,c1 -> (qr, 2qc..); c2,c3 -> (qr+8, ...)
#pragma unroll
    for (int mi = 0; mi < 4; mi++) {
        const int r0 = rowBase + wm + mi * 16 + qr;
        const int r1 = r0 + 8;
#pragma unroll
        for (int ni = 0; ni < 8; ni++) {
            const int col = colBase + wn + ni * 8 + 2 * qc;
            if (r0 < N_NODES) {
                __half2 h = __floats2half2_rn(acc[mi][ni][0], acc[mi][ni][1]);
                *reinterpret_cast<__half2*>(&g_xw[(size_t)r0 * N_FEAT + col]) = h;
            }
            if (r1 < N_NODES) {
                __half2 h = __floats2half2_rn(acc[mi][ni][2], acc[mi][ni][3]);
                *reinterpret_cast<__half2*>(&g_xw[(size_t)r1 * N_FEAT + col]) = h;
            }
        }
    }
}

// ---------------------------------------------------------------------------
// Fused aggregate + bias + relu + softmax. One warp per node; row gathers via
// __ldcg (L2-only: no L1 reuse), metadata via __ldcs, output via __stcs so the
// streaming traffic doesn't evict the g_xw working set from L2.
// ---------------------------------------------------------------------------
__device__ __forceinline__ void acc_half8(float4& a0, float4& a1, uint4 raw, float m) {
    __half2 h0 = *reinterpret_cast<__half2*>(&raw.x);
    __half2 h1 = *reinterpret_cast<__half2*>(&raw.y);
    __half2 h2 = *reinterpret_cast<__half2*>(&raw.z);
    __half2 h3 = *reinterpret_cast<__half2*>(&raw.w);
    float2 f0 = __half22float2(h0);
    float2 f1 = __half22float2(h1);
    float2 f2 = __half22float2(h2);
    float2 f3 = __half22float2(h3);
    a0.x = fmaf(f0.x, m, a0.x); a0.y = fmaf(f0.y, m, a0.y);
    a0.z = fmaf(f1.x, m, a0.z); a0.w = fmaf(f1.y, m, a0.w);
    a1.x = fmaf(f2.x, m, a1.x); a1.y = fmaf(f2.y, m, a1.y);
    a1.z = fmaf(f3.x, m, a1.z); a1.w = fmaf(f3.y, m, a1.w);
}

__global__ __launch_bounds__(256) void aggregate_kernel(const float* __restrict__ bias,
                                                        float* __restrict__ out) {
    const int n = blockIdx.x * 8 + (threadIdx.x >> 5);
    if (n >= N_NODES) return;
    const int lane = threadIdx.x & 31;
    const float dn = g_dinv[n];
    const uint4* __restrict__ xw4 = reinterpret_cast<const uint4*>(g_xw);

    // chunks lane and lane+32 of the 64 uint4 per row
    const size_t rb = (size_t)n * NCH16;
    float4 A0 = make_float4(0.f, 0.f, 0.f, 0.f), A1 = A0;   // chunk lane
    float4 B0 = A0, B1 = A0;                                 // chunk lane+32
    acc_half8(A0, A1, __ldcg(xw4 + rb + lane), dn * dn);     // self loop
    acc_half8(B0, B1, __ldcg(xw4 + rb + lane + 32), dn * dn);

    const int start = g_off[n];
    const int cnt = g_deg[n];
    const int* __restrict__ lst = g_csr_src + start;
    const float* __restrict__ nrm = g_csr_norm + start;

    int i = 0;
    for (; i + 4 <= cnt; i += 4) {
        int s0 = __ldcs(lst + i),     s1 = __ldcs(lst + i + 1);
        int s2 = __ldcs(lst + i + 2), s3 = __ldcs(lst + i + 3);
        float m0 = __ldcs(nrm + i),     m1 = __ldcs(nrm + i + 1);
        float m2 = __ldcs(nrm + i + 2), m3 = __ldcs(nrm + i + 3);
        size_t r0 = (size_t)s0 * NCH16, r1 = (size_t)s1 * NCH16;
        size_t r2 = (size_t)s2 * NCH16, r3 = (size_t)s3 * NCH16;
        uint4 va0 = __ldcg(xw4 + r0 + lane),      va1 = __ldcg(xw4 + r1 + lane);
        uint4 va2 = __ldcg(xw4 + r2 + lane),      va3 = __ldcg(xw4 + r3 + lane);
        uint4 vb0 = __ldcg(xw4 + r0 + lane + 32), vb1 = __ldcg(xw4 + r1 + lane + 32);
        uint4 vb2 = __ldcg(xw4 + r2 + lane + 32), vb3 = __ldcg(xw4 + r3 + lane + 32);
        acc_half8(A0, A1, va0, m0); acc_half8(B0, B1, vb0, m0);
        acc_half8(A0, A1, va1, m1); acc_half8(B0, B1, vb1, m1);
        acc_half8(A0, A1, va2, m2); acc_half8(B0, B1, vb2, m2);
        acc_half8(A0, A1, va3, m3); acc_half8(B0, B1, vb3, m3);
    }
    for (; i < cnt; i++) {
        int s = __ldcs(lst + i);
        float m = __ldcs(nrm + i);
        size_t r = (size_t)s * NCH16;
        acc_half8(A0, A1, __ldcg(xw4 + r + lane), m);
        acc_half8(B0, B1, __ldcg(xw4 + r + lane + 32), m);
    }

    // bias + relu
    const float4* b4 = reinterpret_cast<const float4*>(bias);
    float4 ba0 = b4[2 * lane], ba1 = b4[2 * lane + 1];
    float4 bb0 = b4[2 * (lane + 32)], bb1 = b4[2 * (lane + 32) + 1];
    A0.x = fmaxf(A0.x + ba0.x, 0.f); A0.y = fmaxf(A0.y + ba0.y, 0.f);
    A0.z = fmaxf(A0.z + ba0.z, 0.f); A0.w = fmaxf(A0.w + ba0.w, 0.f);
    A1.x = fmaxf(A1.x + ba1.x, 0.f); A1.y = fmaxf(A1.y + ba1.y, 0.f);
    A1.z = fmaxf(A1.z + ba1.z, 0.f); A1.w = fmaxf(A1.w + ba1.w, 0.f);
    B0.x = fmaxf(B0.x + bb0.x, 0.f); B0.y = fmaxf(B0.y + bb0.y, 0.f);
    B0.z = fmaxf(B0.z + bb0.z, 0.f); B0.w = fmaxf(B0.w + bb0.w, 0.f);
    B1.x = fmaxf(B1.x + bb1.x, 0.f); B1.y = fmaxf(B1.y + bb1.y, 0.f);
    B1.z = fmaxf(B1.z + bb1.z, 0.f); B1.w = fmaxf(B1.w + bb1.w, 0.f);

    // softmax over 512 = warp shuffles only
    float m = fmaxf(fmaxf(fmaxf(A0.x, A0.y), fmaxf(A0.z, A0.w)),
                    fmaxf(fmaxf(A1.x, A1.y), fmaxf(A1.z, A1.w)));
    m = fmaxf(m, fmaxf(fmaxf(fmaxf(B0.x, B0.y), fmaxf(B0.z, B0.w)),
                       fmaxf(fmaxf(B1.x, B1.y), fmaxf(B1.z, B1.w))));
#pragma unroll
    for (int o = 16; o > 0; o >>= 1)
        m = fmaxf(m, __shfl_xor_sync(0xFFFFFFFF, m, o));

    A0.x = __expf(A0.x - m); A0.y = __expf(A0.y - m);
    A0.z = __expf(A0.z - m); A0.w = __expf(A0.w - m);
    A1.x = __expf(A1.x - m); A1.y = __expf(A1.y - m);
    A1.z = __expf(A1.z - m); A1.w = __expf(A1.w - m);
    B0.x = __expf(B0.x - m); B0.y = __expf(B0.y - m);
    B0.z = __expf(B0.z - m); B0.w = __expf(B0.w - m);
    B1.x = __expf(B1.x - m); B1.y = __expf(B1.y - m);
    B1.z = __expf(B1.z - m); B1.w = __expf(B1.w - m);

    float s = A0.x + A0.y + A0.z + A0.w + A1.x + A1.y + A1.z + A1.w +
              B0.x + B0.y + B0.z + B0.w + B1.x + B1.y + B1.z + B1.w;
#pragma unroll
    for (int o = 16; o > 0; o >>= 1)
        s += __shfl_xor_sync(0xFFFFFFFF, s, o);

    float inv = __frcp_rn(s);
    A0.x *= inv; A0.y *= inv; A0.z *= inv; A0.w *= inv;
    A1.x *= inv; A1.y *= inv; A1.z *= inv; A1.w *= inv;
    B0.x *= inv; B0.y *= inv; B0.z *= inv; B0.w *= inv;
    B1.x *= inv; B1.y *= inv; B1.z *= inv; B1.w *= inv;

    float4* orow = reinterpret_cast<float4*>(out) + (size_t)n * (N_FEAT / 4);
    __stcs(orow + 2 * lane,            A0);
    __stcs(orow + 2 * lane + 1,        A1);
    __stcs(orow + 2 * (lane + 32),     B0);
    __stcs(orow + 2 * (lane + 32) + 1, B1);
}

// ---------------------------------------------------------------------------
// Launch. CSR build forked onto a side stream; GEMM kept as 4th submitted
// launch for the ncu slot.
// ---------------------------------------------------------------------------
extern "C" void kernel_launch(void* const* d_in, const int* in_sizes, int n_in,
                              void* d_out, int out_size) {
    const float* onehot = (const float*)d_in[0];
    const int*   ei     = (const int*)d_in[1];    // [2, E]: src then dst
    const float* W      = (const float*)d_in[2];
    const float* b      = (const float*)d_in[3];
    float* out = (float*)d_out;

    static cudaStream_t side = nullptr;
    static cudaEvent_t evFork = nullptr, evJoin = nullptr;
    if (!side) {
        cudaStreamCreateWithFlags(&side, cudaStreamNonBlocking);
        cudaEventCreateWithFlags(&evFork, cudaEventDisableTiming);
        cudaEventCreateWithFlags(&evJoin, cudaEventDisableTiming);
        cudaFuncSetAttribute(gemm_kernel, cudaFuncAttributeMaxDynamicSharedMemorySize, SMEM_DYN);
    }

    // fork: side branch handles the CSR build
    cudaEventRecord(evFork, 0);
    cudaStreamWaitEvent(side, evFork, 0);

    cvtW_kernel<<<(N_FEAT * N_FEAT / 8 + 255) / 256, 256>>>(W);                     // #1
    zero_kernel<<<(N_NODES + 255) / 256, 256, 0, side>>>();                         // #2
    count_deg_kernel<<<(N_EDGES + 255) / 256, 256, 0, side>>>(ei + N_EDGES);        // #3
    gemm_kernel<<<dim3(N_FEAT / BN, (N_NODES + BM - 1) / BM), 256, SMEM_DYN>>>(onehot); // #4
    alloc_kernel<<<(N_NODES + 255) / 256, 256, 0, side>>>();
    fill_kernel<<<(N_EDGES + 255) / 256, 256, 0, side>>>(ei);

    // join: aggregate needs both the GEMM (main) and the CSR (side)
    cudaEventRecord(evJoin, side);
    cudaStreamWaitEvent(0, evJoin, 0);

    aggregate_kernel<<<(N_NODES + 7) / 8, 256>>>(b, out);
}

// round 12
// speedup vs baseline: 1.0528x; 1.0427x over previous
#include <cuda_runtime.h>
#include <cuda_fp16.h>
#include <cstdint>

#define N_NODES 100000
#define N_FEAT  512
#define N_EDGES 3200000
#define NCH16   (N_FEAT / 8)   // 64 uint4 (8-half) chunks per row

// Scratch (allocation-free rule: __device__ globals)
__device__ __half g_wh[(size_t)N_FEAT * N_FEAT];   // W in fp16
__device__ __half g_xw[(size_t)N_NODES * N_FEAT];  // X @ W in fp16
__device__ float g_dinv[N_NODES];                  // rsqrt(deg+1)
__device__ int   g_deg[N_NODES];                   // in-degree (no self loop)
__device__ int   g_off[N_NODES];                   // CSR chunk start
__device__ int   g_cursor[N_NODES];                // fill cursor
__device__ int   g_csr_src[N_EDGES];               // src ids grouped by dst
__device__ float g_csr_norm[N_EDGES];              // dinv[src]*dinv[dst]
__device__ int   g_total;                          // chunk allocator

// ---------------------------------------------------------------------------
// fp32 -> fp16 helpers
// ---------------------------------------------------------------------------
__device__ __forceinline__ uint4 cvt8(const float4 a, const float4 b) {
    __half2 h0 = __floats2half2_rn(a.x, a.y);
    __half2 h1 = __floats2half2_rn(a.z, a.w);
    __half2 h2 = __floats2half2_rn(b.x, b.y);
    __half2 h3 = __floats2half2_rn(b.z, b.w);
    uint4 v;
    v.x = *reinterpret_cast<unsigned*>(&h0);
    v.y = *reinterpret_cast<unsigned*>(&h1);
    v.z = *reinterpret_cast<unsigned*>(&h2);
    v.w = *reinterpret_cast<unsigned*>(&h3);
    return v;
}

__global__ void cvtW_kernel(const float* __restrict__ W) {
    int i = blockIdx.x * blockDim.x + threadIdx.x;   // over 512*512/8
    if (i < N_FEAT * N_FEAT / 8) {
        const float4* s = reinterpret_cast<const float4*>(W) + 2 * (size_t)i;
        reinterpret_cast<uint4*>(g_wh)[i] = cvt8(s[0], s[1]);
    }
}

// ---------------------------------------------------------------------------
// CSR build
// ---------------------------------------------------------------------------
__global__ void zero_kernel() {
    int i = blockIdx.x * blockDim.x + threadIdx.x;
    if (i < N_NODES) g_deg[i] = 0;
    if (i == 0) g_total = 0;
}

__global__ void count_deg_kernel(const int* __restrict__ dst) {
    int e = blockIdx.x * blockDim.x + threadIdx.x;
    if (e < N_EDGES) atomicAdd(&g_deg[__ldcs(dst + e)], 1);
}

__global__ void alloc_kernel() {
    int i = blockIdx.x * blockDim.x + threadIdx.x;
    if (i < N_NODES) {
        int d = g_deg[i];
        int o = atomicAdd(&g_total, d);   // disjoint contiguous ranges
        g_off[i] = o;
        g_cursor[i] = o;
        g_dinv[i] = rsqrtf((float)d + 1.0f);  // +1 = self loop
    }
}

__global__ void fill_kernel(const int* __restrict__ ei) {
    int e = blockIdx.x * blockDim.x + threadIdx.x;
    if (e < N_EDGES) {
        int s = __ldcs(ei + e);
        int d = __ldcs(ei + N_EDGES + e);
        int pos = atomicAdd(&g_cursor[d], 1);
        g_csr_src[pos] = s;
        g_csr_norm[pos] = g_dinv[s] * g_dinv[d];   // dinv ready (fill after alloc)
    }
}

// ---------------------------------------------------------------------------
// GEMM: g_xw = fp16(onehot @ g_wh), fp16 mma m16n8k16 with fp32 accumulate.
// Launched twice (pass = column half) so aggregation can start after half 1.
// 256x128x32 block tile, 256 threads = 8 warps (4m x 2n), warp tile 64x64.
// ---------------------------------------------------------------------------
#define BM 256
#define BN 128
#define BK 32
#define SAH 40    // A smem row stride (halves)
#define SBH 136   // B smem row stride (halves)
#define A_BUF_H (BM * SAH)              // 10240 halves per buffer
#define B_BASE_H (2 * A_BUF_H)          // 20480
#define B_BUF_H (BK * SBH)              // 4352 halves per buffer
#define SMEM_DYN ((B_BASE_H + 2 * B_BUF_H) * 2)  // 58368 bytes

__device__ __forceinline__ unsigned smem_u32(const void* p) {
    return (unsigned)__cvta_generic_to_shared(p);
}

__device__ __forceinline__ void ldsm_x4(unsigned* r, const void* p) {
    asm volatile("ldmatrix.sync.aligned.m8n8.x4.shared.b16 {%0,%1,%2,%3}, [%4];"
                 : "=r"(r[0]), "=r"(r[1]), "=r"(r[2]), "=r"(r[3]) : "r"(smem_u32(p)));
}

__device__ __forceinline__ void ldsm_x4_trans(unsigned* r, const void* p) {
    asm volatile("ldmatrix.sync.aligned.m8n8.x4.trans.shared.b16 {%0,%1,%2,%3}, [%4];"
                 : "=r"(r[0]), "=r"(r[1]), "=r"(r[2]), "=r"(r[3]) : "r"(smem_u32(p)));
}

__device__ __forceinline__ void mma_f16(float* c, const unsigned* a, const unsigned* b) {
    asm volatile(
        "mma.sync.aligned.m16n8k16.row.col.f32.f16.f16.f32 "
        "{%0,%1,%2,%3}, {%4,%5,%6,%7}, {%8,%9}, {%0,%1,%2,%3};"
        : "+f"(c[0]), "+f"(c[1]), "+f"(c[2]), "+f"(c[3])
        : "r"(a[0]), "r"(a[1]), "r"(a[2]), "r"(a[3]), "r"(b[0]), "r"(b[1]));
}

__global__ __launch_bounds__(256, 1) void gemm_kernel(const float* __restrict__ A, int pass) {
    extern __shared__ __half sm[];

    const int tid = threadIdx.x;
    const int rowBase = blockIdx.y * BM;
    const int colBase = (blockIdx.x + 2 * pass) * BN;

    // A: 256 rows x 32 fp32, per thread 8 fp32 (2 float4) per row-slice i.
    const int arow = tid >> 2;            // 0..63 (+64*i)
    const int akc  = (tid & 3) * 8;       // 0,8,16,24
    // B: 32 k x 128 n fp16, per thread 8 halves per slice j.
    const int bk   = tid >> 4;            // 0..15 (+16*j)
    const int bn   = (tid & 15) * 8;      // 0..120

    const float*  Aptr = A + (size_t)(rowBase + arow) * N_FEAT + akc;
    const __half* Bptr = g_wh + (size_t)bk * N_FEAT + colBase + bn;

    bool aok[4];
#pragma unroll
    for (int i = 0; i < 4; i++) aok[i] = (rowBase + arow + 64 * i) < N_NODES;

    // Warp tiling: 8 warps as 4(m) x 2(n); warp tile 64x64.
    const int warpId = tid >> 5;
    const int lane = tid & 31;
    const int wm = (warpId >> 1) * 64;    // 0,64,128,192
    const int wn = (warpId & 1) * 64;     // 0,64
    const int lr = lane & 15;             // ldmatrix row
    const int lc = (lane >> 4) * 8;       // ldmatrix col block
    const int qr = lane >> 2;             // mma c row
    const int qc = lane & 3;              // mma c col pair

    float acc[4][8][4] = {};              // [mi][ni][reg]

    float4 aR[4][2];
    uint4 bR[2];
#pragma unroll
    for (int i = 0; i < 4; i++) {
        if (aok[i]) {
            aR[i][0] = __ldcs(reinterpret_cast<const float4*>(Aptr + (size_t)64 * i * N_FEAT));
            aR[i][1] = __ldcs(reinterpret_cast<const float4*>(Aptr + (size_t)64 * i * N_FEAT + 4));
        } else {
            aR[i][0] = aR[i][1] = make_float4(0.f, 0.f, 0.f, 0.f);
        }
    }
#pragma unroll
    for (int j = 0; j < 2; j++)
        bR[j] = *reinterpret_cast<const uint4*>(Bptr + (size_t)16 * j * N_FEAT);

    int buf = 0;
    for (int kb = 0; kb < N_FEAT; kb += BK) {
        // store prefetched tile (convert A to fp16 here)
#pragma unroll
        for (int i = 0; i < 4; i++)
            *reinterpret_cast<uint4*>(&sm[buf * A_BUF_H + (arow + 64 * i) * SAH + akc]) =
                cvt8(aR[i][0], aR[i][1]);
#pragma unroll
        for (int j = 0; j < 2; j++)
            *reinterpret_cast<uint4*>(&sm[B_BASE_H + buf * B_BUF_H + (bk + 16 * j) * SBH + bn]) = bR[j];
        __syncthreads();

        // prefetch next tile
        if (kb + BK < N_FEAT) {
#pragma unroll
            for (int i = 0; i < 4; i++)
                if (aok[i]) {
                    aR[i][0] = __ldcs(reinterpret_cast<const float4*>(
                        Aptr + (size_t)64 * i * N_FEAT + kb + BK));
                    aR[i][1] = __ldcs(reinterpret_cast<const float4*>(
                        Aptr + (size_t)64 * i * N_FEAT + kb + BK + 4));
                }
#pragma unroll
            for (int j = 0; j < 2; j++)
                bR[j] = *reinterpret_cast<const uint4*>(
                    Bptr + (size_t)(kb + BK + 16 * j) * N_FEAT);
        }

#pragma unroll
        for (int ks = 0; ks < 2; ks++) {
            const int k0 = ks * 16;
            unsigned af[4][4];
#pragma unroll
            for (int mi = 0; mi < 4; mi++)
                ldsm_x4(af[mi], &sm[buf * A_BUF_H + (wm + mi * 16 + lr) * SAH + k0 + lc]);
            unsigned bf[4][4];
#pragma unroll
            for (int nj = 0; nj < 4; nj++)
                ldsm_x4_trans(bf[nj], &sm[B_BASE_H + buf * B_BUF_H + (k0 + lr) * SBH + wn + nj * 16 + lc]);
#pragma unroll
            for (int mi = 0; mi < 4; mi++)
#pragma unroll
                for (int ni = 0; ni < 8; ni++)
                    mma_f16(acc[mi][ni], af[mi], &bf[ni >> 1][(ni & 1) * 2]);
        }
        __syncthreads();
        buf ^= 1;
    }

    // Epilogue: fp16 stores. c0,c1 -> (qr, 2qc..); c2,c3 -> (qr+8, ...)
#pragma unroll
    for (int mi = 0; mi < 4; mi++) {
        const int r0 = rowBase + wm + mi * 16 + qr;
        const int r1 = r0 + 8;
#pragma unroll
        for (int ni = 0; ni < 8; ni++) {
            const int col = colBase + wn + ni * 8 + 2 * qc;
            if (r0 < N_NODES) {
                __half2 h = __floats2half2_rn(acc[mi][ni][0], acc[mi][ni][1]);
                *reinterpret_cast<__half2*>(&g_xw[(size_t)r0 * N_FEAT + col]) = h;
            }
            if (r1 < N_NODES) {
                __half2 h = __floats2half2_rn(acc[mi][ni][2], acc[mi][ni][3]);
                *reinterpret_cast<__half2*>(&g_xw[(size_t)r1 * N_FEAT + col]) = h;
            }
        }
    }
}

// ---------------------------------------------------------------------------
// Aggregate one COLUMN HALF (256 features): gather + bias + relu, write
// pre-softmax logits to out. One warp per node, lane owns one uint4 (8 halves).
// The 51 MB half of g_xw is fully L2-resident -> gathers are L2 hits.
// ---------------------------------------------------------------------------
__device__ __forceinline__ void acc_half8(float4& a0, float4& a1, uint4 raw, float m) {
    __half2 h0 = *reinterpret_cast<__half2*>(&raw.x);
    __half2 h1 = *reinterpret_cast<__half2*>(&raw.y);
    __half2 h2 = *reinterpret_cast<__half2*>(&raw.z);
    __half2 h3 = *reinterpret_cast<__half2*>(&raw.w);
    float2 f0 = __half22float2(h0);
    float2 f1 = __half22float2(h1);
    float2 f2 = __half22float2(h2);
    float2 f3 = __half22float2(h3);
    a0.x = fmaf(f0.x, m, a0.x); a0.y = fmaf(f0.y, m, a0.y);
    a0.z = fmaf(f1.x, m, a0.z); a0.w = fmaf(f1.y, m, a0.w);
    a1.x = fmaf(f2.x, m, a1.x); a1.y = fmaf(f2.y, m, a1.y);
    a1.z = fmaf(f3.x, m, a1.z); a1.w = fmaf(f3.y, m, a1.w);
}

__global__ __launch_bounds__(256) void aggregate_half_kernel(const float* __restrict__ bias,
                                                             float* __restrict__ out,
                                                             int half) {
    const int n = blockIdx.x * 8 + (threadIdx.x >> 5);
    if (n >= N_NODES) return;
    const int lane = threadIdx.x & 31;
    const int chunk = half * 32 + lane;     // uint4 index within the row
    const float dn = g_dinv[n];
    const uint4* __restrict__ xw4 = reinterpret_cast<const uint4*>(g_xw);

    float4 A0 = make_float4(0.f, 0.f, 0.f, 0.f), A1 = A0;
    acc_half8(A0, A1, __ldcg(xw4 + (size_t)n * NCH16 + chunk), dn * dn);   // self loop

    const int start = g_off[n];
    const int cnt = g_deg[n];
    const int* __restrict__ lst = g_csr_src + start;
    const float* __restrict__ nrm = g_csr_norm + start;

    int i = 0;
    for (; i + 8 <= cnt; i += 8) {
        int s0 = __ldcs(lst + i),     s1 = __ldcs(lst + i + 1);
        int s2 = __ldcs(lst + i + 2), s3 = __ldcs(lst + i + 3);
        int s4 = __ldcs(lst + i + 4), s5 = __ldcs(lst + i + 5);
        int s6 = __ldcs(lst + i + 6), s7 = __ldcs(lst + i + 7);
        uint4 v0 = __ldcg(xw4 + (size_t)s0 * NCH16 + chunk);
        uint4 v1 = __ldcg(xw4 + (size_t)s1 * NCH16 + chunk);
        uint4 v2 = __ldcg(xw4 + (size_t)s2 * NCH16 + chunk);
        uint4 v3 = __ldcg(xw4 + (size_t)s3 * NCH16 + chunk);
        uint4 v4 = __ldcg(xw4 + (size_t)s4 * NCH16 + chunk);
        uint4 v5 = __ldcg(xw4 + (size_t)s5 * NCH16 + chunk);
        uint4 v6 = __ldcg(xw4 + (size_t)s6 * NCH16 + chunk);
        uint4 v7 = __ldcg(xw4 + (size_t)s7 * NCH16 + chunk);
        acc_half8(A0, A1, v0, __ldcs(nrm + i));
        acc_half8(A0, A1, v1, __ldcs(nrm + i + 1));
        acc_half8(A0, A1, v2, __ldcs(nrm + i + 2));
        acc_half8(A0, A1, v3, __ldcs(nrm + i + 3));
        acc_half8(A0, A1, v4, __ldcs(nrm + i + 4));
        acc_half8(A0, A1, v5, __ldcs(nrm + i + 5));
        acc_half8(A0, A1, v6, __ldcs(nrm + i + 6));
        acc_half8(A0, A1, v7, __ldcs(nrm + i + 7));
    }
    for (; i < cnt; i++) {
        int s = __ldcs(lst + i);
        acc_half8(A0, A1, __ldcg(xw4 + (size_t)s * NCH16 + chunk), __ldcs(nrm + i));
    }

    // bias + relu, store pre-softmax logits
    const float4* b4 = reinterpret_cast<const float4*>(bias);
    float4 ba0 = b4[2 * chunk], ba1 = b4[2 * chunk + 1];
    A0.x = fmaxf(A0.x + ba0.x, 0.f); A0.y = fmaxf(A0.y + ba0.y, 0.f);
    A0.z = fmaxf(A0.z + ba0.z, 0.f); A0.w = fmaxf(A0.w + ba0.w, 0.f);
    A1.x = fmaxf(A1.x + ba1.x, 0.f); A1.y = fmaxf(A1.y + ba1.y, 0.f);
    A1.z = fmaxf(A1.z + ba1.z, 0.f); A1.w = fmaxf(A1.w + ba1.w, 0.f);

    float4* orow = reinterpret_cast<float4*>(out) + (size_t)n * (N_FEAT / 4);
    __stcs(orow + 2 * chunk,     A0);
    __stcs(orow + 2 * chunk + 1, A1);
}

// ---------------------------------------------------------------------------
// In-place softmax over each 512-wide row. One warp per node.
// ---------------------------------------------------------------------------
__global__ __launch_bounds__(256) void softmax_kernel(float* __restrict__ out) {
    const int n = blockIdx.x * 8 + (threadIdx.x >> 5);
    if (n >= N_NODES) return;
    const int lane = threadIdx.x & 31;
    float4* row = reinterpret_cast<float4*>(out) + (size_t)n * (N_FEAT / 4);

    float4 v[4];
    float m = 0.0f;   // relu output >= 0
#pragma unroll
    for (int j = 0; j < 4; j++) {
        v[j] = __ldcg(row + lane + 32 * j);
        m = fmaxf(m, fmaxf(fmaxf(v[j].x, v[j].y), fmaxf(v[j].z, v[j].w)));
    }
#pragma unroll
    for (int o = 16; o > 0; o >>= 1)
        m = fmaxf(m, __shfl_xor_sync(0xFFFFFFFF, m, o));

    float s = 0.0f;
#pragma unroll
    for (int j = 0; j < 4; j++) {
        v[j].x = __expf(v[j].x - m); v[j].y = __expf(v[j].y - m);
        v[j].z = __expf(v[j].z - m); v[j].w = __expf(v[j].w - m);
        s += v[j].x + v[j].y + v[j].z + v[j].w;
    }
#pragma unroll
    for (int o = 16; o > 0; o >>= 1)
        s += __shfl_xor_sync(0xFFFFFFFF, s, o);

    float inv = __frcp_rn(s);
#pragma unroll
    for (int j = 0; j < 4; j++) {
        v[j].x *= inv; v[j].y *= inv; v[j].z *= inv; v[j].w *= inv;
        __stcs(row + lane + 32 * j, v[j]);
    }
}

// ---------------------------------------------------------------------------
// Launch graph:
//   main: cvtW -> gemmA(evA) -> gemmB(evB)
//   side: zero -> count -> alloc -> fill -> [wait evA] agg1 -> [wait evB]
//         agg2 -> softmax -> (join main)
// gemmA is the 4th submitted launch (ncu slot).
// ---------------------------------------------------------------------------
extern "C" void kernel_launch(void* const* d_in, const int* in_sizes, int n_in,
                              void* d_out, int out_size) {
    const float* onehot = (const float*)d_in[0];
    const int*   ei     = (const int*)d_in[1];    // [2, E]: src then dst
    const float* W      = (const float*)d_in[2];
    const float* b      = (const float*)d_in[3];
    float* out = (float*)d_out;

    static cudaStream_t side = nullptr;
    static cudaEvent_t evFork = nullptr, evA = nullptr, evB = nullptr, evJoin = nullptr;
    if (!side) {
        cudaStreamCreateWithFlags(&side, cudaStreamNonBlocking);
        cudaEventCreateWithFlags(&evFork, cudaEventDisableTiming);
        cudaEventCreateWithFlags(&evA, cudaEventDisableTiming);
        cudaEventCreateWithFlags(&evB, cudaEventDisableTiming);
        cudaEventCreateWithFlags(&evJoin, cudaEventDisableTiming);
        cudaFuncSetAttribute(gemm_kernel, cudaFuncAttributeMaxDynamicSharedMemorySize, SMEM_DYN);
    }

    cudaEventRecord(evFork, 0);
    cudaStreamWaitEvent(side, evFork, 0);

    cvtW_kernel<<<(N_FEAT * N_FEAT / 8 + 255) / 256, 256>>>(W);                     // #1
    zero_kernel<<<(N_NODES + 255) / 256, 256, 0, side>>>();                         // #2
    count_deg_kernel<<<(N_EDGES + 255) / 256, 256, 0, side>>>(ei + N_EDGES);        // #3
    gemm_kernel<<<dim3(2, (N_NODES + BM - 1) / BM), 256, SMEM_DYN>>>(onehot, 0);    // #4 (ncu)
    cudaEventRecord(evA, 0);
    gemm_kernel<<<dim3(2, (N_NODES + BM - 1) / BM), 256, SMEM_DYN>>>(onehot, 1);
    cudaEventRecord(evB, 0);

    alloc_kernel<<<(N_NODES + 255) / 256, 256, 0, side>>>();
    fill_kernel<<<(N_EDGES + 255) / 256, 256, 0, side>>>(ei);

    cudaStreamWaitEvent(side, evA, 0);
    aggregate_half_kernel<<<(N_NODES + 7) / 8, 256, 0, side>>>(b, out, 0);
    cudaStreamWaitEvent(side, evB, 0);
    aggregate_half_kernel<<<(N_NODES + 7) / 8, 256, 0, side>>>(b, out, 1);
    softmax_kernel<<<(N_NODES + 7) / 8, 256, 0, side>>>(out);

    cudaEventRecord(evJoin, side);
    cudaStreamWaitEvent(0, evJoin, 0);
}

// round 13
// speedup vs baseline: 1.0709x; 1.0172x over previous
#include <cuda_runtime.h>
#include <cuda_fp16.h>
#include <cstdint>

#define N_NODES 100000
#define N_FEAT  512
#define N_EDGES 3200000
#define NCH16   (N_FEAT / 8)   // 64 uint4 (8-half) chunks per row

// Scratch (allocation-free rule: __device__ globals)
__device__ __half g_wh[(size_t)N_FEAT * N_FEAT];   // W in fp16
__device__ __half g_xw[(size_t)N_NODES * N_FEAT];  // X @ W in fp16
__device__ float g_dinv[N_NODES];                  // rsqrt(deg+1)
__device__ int   g_deg[N_NODES];                   // in-degree (no self loop)
__device__ int   g_off[N_NODES];                   // CSR chunk start
__device__ int   g_cursor[N_NODES];                // fill cursor
__device__ int2  g_csr[N_EDGES];                   // {src, norm-bits} grouped by dst
__device__ int   g_total;                          // chunk allocator

// ---------------------------------------------------------------------------
// fp32 -> fp16 helpers
// ---------------------------------------------------------------------------
__device__ __forceinline__ uint4 cvt8(const float4 a, const float4 b) {
    __half2 h0 = __floats2half2_rn(a.x, a.y);
    __half2 h1 = __floats2half2_rn(a.z, a.w);
    __half2 h2 = __floats2half2_rn(b.x, b.y);
    __half2 h3 = __floats2half2_rn(b.z, b.w);
    uint4 v;
    v.x = *reinterpret_cast<unsigned*>(&h0);
    v.y = *reinterpret_cast<unsigned*>(&h1);
    v.z = *reinterpret_cast<unsigned*>(&h2);
    v.w = *reinterpret_cast<unsigned*>(&h3);
    return v;
}

__global__ void cvtW_kernel(const float* __restrict__ W) {
    int i = blockIdx.x * blockDim.x + threadIdx.x;   // over 512*512/8
    if (i < N_FEAT * N_FEAT / 8) {
        const float4* s = reinterpret_cast<const float4*>(W) + 2 * (size_t)i;
        reinterpret_cast<uint4*>(g_wh)[i] = cvt8(s[0], s[1]);
    }
}

// ---------------------------------------------------------------------------
// CSR build
// ---------------------------------------------------------------------------
__global__ void zero_kernel() {
    int i = blockIdx.x * blockDim.x + threadIdx.x;
    if (i < N_NODES) g_deg[i] = 0;
    if (i == 0) g_total = 0;
}

__global__ void count_deg_kernel(const int* __restrict__ dst) {
    int e = blockIdx.x * blockDim.x + threadIdx.x;
    if (e < N_EDGES) atomicAdd(&g_deg[__ldcs(dst + e)], 1);
}

__global__ void alloc_kernel() {
    int i = blockIdx.x * blockDim.x + threadIdx.x;
    if (i < N_NODES) {
        int d = g_deg[i];
        int o = atomicAdd(&g_total, d);   // disjoint contiguous ranges
        g_off[i] = o;
        g_cursor[i] = o;
        g_dinv[i] = rsqrtf((float)d + 1.0f);  // +1 = self loop
    }
}

__global__ void fill_kernel(const int* __restrict__ ei) {
    int e = blockIdx.x * blockDim.x + threadIdx.x;
    if (e < N_EDGES) {
        int s = __ldcs(ei + e);
        int d = __ldcs(ei + N_EDGES + e);
        int pos = atomicAdd(&g_cursor[d], 1);
        float nm = g_dinv[s] * g_dinv[d];   // dinv ready (fill after alloc)
        g_csr[pos] = make_int2(s, __float_as_int(nm));
    }
}

// ---------------------------------------------------------------------------
// GEMM: g_xw = fp16(onehot @ g_wh), fp16 mma m16n8k16 with fp32 accumulate.
// Launched twice (pass = column half) so aggregation can start after half 1.
// 256x128x32 block tile, 256 threads = 8 warps (4m x 2n), warp tile 64x64.
// ---------------------------------------------------------------------------
#define BM 256
#define BN 128
#define BK 32
#define SAH 40    // A smem row stride (halves)
#define SBH 136   // B smem row stride (halves)
#define A_BUF_H (BM * SAH)              // 10240 halves per buffer
#define B_BASE_H (2 * A_BUF_H)          // 20480
#define B_BUF_H (BK * SBH)              // 4352 halves per buffer
#define SMEM_DYN ((B_BASE_H + 2 * B_BUF_H) * 2)  // 58368 bytes

__device__ __forceinline__ unsigned smem_u32(const void* p) {
    return (unsigned)__cvta_generic_to_shared(p);
}

__device__ __forceinline__ void ldsm_x4(unsigned* r, const void* p) {
    asm volatile("ldmatrix.sync.aligned.m8n8.x4.shared.b16 {%0,%1,%2,%3}, [%4];"
                 : "=r"(r[0]), "=r"(r[1]), "=r"(r[2]), "=r"(r[3]) : "r"(smem_u32(p)));
}

__device__ __forceinline__ void ldsm_x4_trans(unsigned* r, const void* p) {
    asm volatile("ldmatrix.sync.aligned.m8n8.x4.trans.shared.b16 {%0,%1,%2,%3}, [%4];"
                 : "=r"(r[0]), "=r"(r[1]), "=r"(r[2]), "=r"(r[3]) : "r"(smem_u32(p)));
}

__device__ __forceinline__ void mma_f16(float* c, const unsigned* a, const unsigned* b) {
    asm volatile(
        "mma.sync.aligned.m16n8k16.row.col.f32.f16.f16.f32 "
        "{%0,%1,%2,%3}, {%4,%5,%6,%7}, {%8,%9}, {%0,%1,%2,%3};"
        : "+f"(c[0]), "+f"(c[1]), "+f"(c[2]), "+f"(c[3])
        : "r"(a[0]), "r"(a[1]), "r"(a[2]), "r"(a[3]), "r"(b[0]), "r"(b[1]));
}

__global__ __launch_bounds__(256, 1) void gemm_kernel(const float* __restrict__ A, int pass) {
    extern __shared__ __half sm[];

    const int tid = threadIdx.x;
    const int rowBase = blockIdx.y * BM;
    const int colBase = (blockIdx.x + 2 * pass) * BN;

    const int arow = tid >> 2;            // 0..63 (+64*i)
    const int akc  = (tid & 3) * 8;       // 0,8,16,24
    const int bk   = tid >> 4;            // 0..15 (+16*j)
    const int bn   = (tid & 15) * 8;      // 0..120

    const float*  Aptr = A + (size_t)(rowBase + arow) * N_FEAT + akc;
    const __half* Bptr = g_wh + (size_t)bk * N_FEAT + colBase + bn;

    bool aok[4];
#pragma unroll
    for (int i = 0; i < 4; i++) aok[i] = (rowBase + arow + 64 * i) < N_NODES;

    const int warpId = tid >> 5;
    const int lane = tid & 31;
    const int wm = (warpId >> 1) * 64;    // 0,64,128,192
    const int wn = (warpId & 1) * 64;     // 0,64
    const int lr = lane & 15;             // ldmatrix row
    const int lc = (lane >> 4) * 8;       // ldmatrix col block
    const int qr = lane >> 2;             // mma c row
    const int qc = lane & 3;              // mma c col pair

    float acc[4][8][4] = {};              // [mi][ni][reg]

    float4 aR[4][2];
    uint4 bR[2];
#pragma unroll
    for (int i = 0; i < 4; i++) {
        if (aok[i]) {
            aR[i][0] = __ldcs(reinterpret_cast<const float4*>(Aptr + (size_t)64 * i * N_FEAT));
            aR[i][1] = __ldcs(reinterpret_cast<const float4*>(Aptr + (size_t)64 * i * N_FEAT + 4));
        } else {
            aR[i][0] = aR[i][1] = make_float4(0.f, 0.f, 0.f, 0.f);
        }
    }
#pragma unroll
    for (int j = 0; j < 2; j++)
        bR[j] = *reinterpret_cast<const uint4*>(Bptr + (size_t)16 * j * N_FEAT);

    int buf = 0;
    for (int kb = 0; kb < N_FEAT; kb += BK) {
#pragma unroll
        for (int i = 0; i < 4; i++)
            *reinterpret_cast<uint4*>(&sm[buf * A_BUF_H + (arow + 64 * i) * SAH + akc]) =
                cvt8(aR[i][0], aR[i][1]);
#pragma unroll
        for (int j = 0; j < 2; j++)
            *reinterpret_cast<uint4*>(&sm[B_BASE_H + buf * B_BUF_H + (bk + 16 * j) * SBH + bn]) = bR[j];
        __syncthreads();

        if (kb + BK < N_FEAT) {
#pragma unroll
            for (int i = 0; i < 4; i++)
                if (aok[i]) {
                    aR[i][0] = __ldcs(reinterpret_cast<const float4*>(
                        Aptr + (size_t)64 * i * N_FEAT + kb + BK));
                    aR[i][1] = __ldcs(reinterpret_cast<const float4*>(
                        Aptr + (size_t)64 * i * N_FEAT + kb + BK + 4));
                }
#pragma unroll
            for (int j = 0; j < 2; j++)
                bR[j] = *reinterpret_cast<const uint4*>(
                    Bptr + (size_t)(kb + BK + 16 * j) * N_FEAT);
        }

#pragma unroll
        for (int ks = 0; ks < 2; ks++) {
            const int k0 = ks * 16;
            unsigned af[4][4];
#pragma unroll
            for (int mi = 0; mi < 4; mi++)
                ldsm_x4(af[mi], &sm[buf * A_BUF_H + (wm + mi * 16 + lr) * SAH + k0 + lc]);
            unsigned bf[4][4];
#pragma unroll
            for (int nj = 0; nj < 4; nj++)
                ldsm_x4_trans(bf[nj], &sm[B_BASE_H + buf * B_BUF_H + (k0 + lr) * SBH + wn + nj * 16 + lc]);
#pragma unroll
            for (int mi = 0; mi < 4; mi++)
#pragma unroll
                for (int ni = 0; ni < 8; ni++)
                    mma_f16(acc[mi][ni], af[mi], &bf[ni >> 1][(ni & 1) * 2]);
        }
        __syncthreads();
        buf ^= 1;
    }

#pragma unroll
    for (int mi = 0; mi < 4; mi++) {
        const int r0 = rowBase + wm + mi * 16 + qr;
        const int r1 = r0 + 8;
#pragma unroll
        for (int ni = 0; ni < 8; ni++) {
            const int col = colBase + wn + ni * 8 + 2 * qc;
            if (r0 < N_NODES) {
                __half2 h = __floats2half2_rn(acc[mi][ni][0], acc[mi][ni][1]);
                *reinterpret_cast<__half2*>(&g_xw[(size_t)r0 * N_FEAT + col]) = h;
            }
            if (r1 < N_NODES) {
                __half2 h = __floats2half2_rn(acc[mi][ni][2], acc[mi][ni][3]);
                *reinterpret_cast<__half2*>(&g_xw[(size_t)r1 * N_FEAT + col]) = h;
            }
        }
    }
}

// ---------------------------------------------------------------------------
// Aggregate helpers. One warp per node, lane owns one uint4 (8 halves) of the
// 256-feature column half being processed.
// ---------------------------------------------------------------------------
__device__ __forceinline__ void acc_half8(float4& a0, float4& a1, uint4 raw, float m) {
    __half2 h0 = *reinterpret_cast<__half2*>(&raw.x);
    __half2 h1 = *reinterpret_cast<__half2*>(&raw.y);
    __half2 h2 = *reinterpret_cast<__half2*>(&raw.z);
    __half2 h3 = *reinterpret_cast<__half2*>(&raw.w);
    float2 f0 = __half22float2(h0);
    float2 f1 = __half22float2(h1);
    float2 f2 = __half22float2(h2);
    float2 f3 = __half22float2(h3);
    a0.x = fmaf(f0.x, m, a0.x); a0.y = fmaf(f0.y, m, a0.y);
    a0.z = fmaf(f1.x, m, a0.z); a0.w = fmaf(f1.y, m, a0.w);
    a1.x = fmaf(f2.x, m, a1.x); a1.y = fmaf(f2.y, m, a1.y);
    a1.z = fmaf(f3.x, m, a1.z); a1.w = fmaf(f3.y, m, a1.w);
}

// Gathers one column half for node n into (A0, A1), adds bias, applies relu.
__device__ __forceinline__ void gather_half(int n, int chunk, float4& A0, float4& A1,
                                            const float* __restrict__ bias) {
    const float dn = g_dinv[n];
    const uint4* __restrict__ xw4 = reinterpret_cast<const uint4*>(g_xw);

    A0 = make_float4(0.f, 0.f, 0.f, 0.f); A1 = A0;
    acc_half8(A0, A1, __ldcg(xw4 + (size_t)n * NCH16 + chunk), dn * dn);   // self loop

    const int start = g_off[n];
    const int cnt = g_deg[n];
    const int2* __restrict__ lst = g_csr + start;

    int i = 0;
    for (; i + 8 <= cnt; i += 8) {
        int2 e0 = __ldcs(lst + i),     e1 = __ldcs(lst + i + 1);
        int2 e2 = __ldcs(lst + i + 2), e3 = __ldcs(lst + i + 3);
        int2 e4 = __ldcs(lst + i + 4), e5 = __ldcs(lst + i + 5);
        int2 e6 = __ldcs(lst + i + 6), e7 = __ldcs(lst + i + 7);
        uint4 v0 = __ldcg(xw4 + (size_t)e0.x * NCH16 + chunk);
        uint4 v1 = __ldcg(xw4 + (size_t)e1.x * NCH16 + chunk);
        uint4 v2 = __ldcg(xw4 + (size_t)e2.x * NCH16 + chunk);
        uint4 v3 = __ldcg(xw4 + (size_t)e3.x * NCH16 + chunk);
        uint4 v4 = __ldcg(xw4 + (size_t)e4.x * NCH16 + chunk);
        uint4 v5 = __ldcg(xw4 + (size_t)e5.x * NCH16 + chunk);
        uint4 v6 = __ldcg(xw4 + (size_t)e6.x * NCH16 + chunk);
        uint4 v7 = __ldcg(xw4 + (size_t)e7.x * NCH16 + chunk);
        acc_half8(A0, A1, v0, __int_as_float(e0.y));
        acc_half8(A0, A1, v1, __int_as_float(e1.y));
        acc_half8(A0, A1, v2, __int_as_float(e2.y));
        acc_half8(A0, A1, v3, __int_as_float(e3.y));
        acc_half8(A0, A1, v4, __int_as_float(e4.y));
        acc_half8(A0, A1, v5, __int_as_float(e5.y));
        acc_half8(A0, A1, v6, __int_as_float(e6.y));
        acc_half8(A0, A1, v7, __int_as_float(e7.y));
    }
    for (; i < cnt; i++) {
        int2 e = __ldcs(lst + i);
        acc_half8(A0, A1, __ldcg(xw4 + (size_t)e.x * NCH16 + chunk), __int_as_float(e.y));
    }

    const float4* b4 = reinterpret_cast<const float4*>(bias);
    float4 ba0 = b4[2 * chunk], ba1 = b4[2 * chunk + 1];
    A0.x = fmaxf(A0.x + ba0.x, 0.f); A0.y = fmaxf(A0.y + ba0.y, 0.f);
    A0.z = fmaxf(A0.z + ba0.z, 0.f); A0.w = fmaxf(A0.w + ba0.w, 0.f);
    A1.x = fmaxf(A1.x + ba1.x, 0.f); A1.y = fmaxf(A1.y + ba1.y, 0.f);
    A1.z = fmaxf(A1.z + ba1.z, 0.f); A1.w = fmaxf(A1.w + ba1.w, 0.f);
}

// Half 0: write relu'd logits to out (columns 0..255).
__global__ __launch_bounds__(256) void aggregate_half0_kernel(const float* __restrict__ bias,
                                                              float* __restrict__ out) {
    const int n = blockIdx.x * 8 + (threadIdx.x >> 5);
    if (n >= N_NODES) return;
    const int lane = threadIdx.x & 31;
    float4 A0, A1;
    gather_half(n, lane, A0, A1, bias);
    float4* orow = reinterpret_cast<float4*>(out) + (size_t)n * (N_FEAT / 4);
    __stcs(orow + 2 * lane,     A0);
    __stcs(orow + 2 * lane + 1, A1);
}

// Half 1 + fused softmax: gather columns 256..511, re-read half-0 logits,
// normalize the full row, and write everything once.
__global__ __launch_bounds__(256) void aggregate_half1_final_kernel(const float* __restrict__ bias,
                                                                    float* __restrict__ out) {
    const int n = blockIdx.x * 8 + (threadIdx.x >> 5);
    if (n >= N_NODES) return;
    const int lane = threadIdx.x & 31;
    float4 A0, A1;
    gather_half(n, 32 + lane, A0, A1, bias);

    float4* orow = reinterpret_cast<float4*>(out) + (size_t)n * (N_FEAT / 4);
    float4 L0 = __ldcg(orow + 2 * lane);        // half-0 logits (relu'd)
    float4 L1 = __ldcg(orow + 2 * lane + 1);

    // row max (relu output >= 0 so 0 is a valid floor)
    float m = fmaxf(fmaxf(fmaxf(A0.x, A0.y), fmaxf(A0.z, A0.w)),
                    fmaxf(fmaxf(A1.x, A1.y), fmaxf(A1.z, A1.w)));
    m = fmaxf(m, fmaxf(fmaxf(fmaxf(L0.x, L0.y), fmaxf(L0.z, L0.w)),
                       fmaxf(fmaxf(L1.x, L1.y), fmaxf(L1.z, L1.w))));
#pragma unroll
    for (int o = 16; o > 0; o >>= 1)
        m = fmaxf(m, __shfl_xor_sync(0xFFFFFFFF, m, o));

    A0.x = __expf(A0.x - m); A0.y = __expf(A0.y - m);
    A0.z = __expf(A0.z - m); A0.w = __expf(A0.w - m);
    A1.x = __expf(A1.x - m); A1.y = __expf(A1.y - m);
    A1.z = __expf(A1.z - m); A1.w = __expf(A1.w - m);
    L0.x = __expf(L0.x - m); L0.y = __expf(L0.y - m);
    L0.z = __expf(L0.z - m); L0.w = __expf(L0.w - m);
    L1.x = __expf(L1.x - m); L1.y = __expf(L1.y - m);
    L1.z = __expf(L1.z - m); L1.w = __expf(L1.w - m);

    float s = A0.x + A0.y + A0.z + A0.w + A1.x + A1.y + A1.z + A1.w +
              L0.x + L0.y + L0.z + L0.w + L1.x + L1.y + L1.z + L1.w;
#pragma unroll
    for (int o = 16; o > 0; o >>= 1)
        s += __shfl_xor_sync(0xFFFFFFFF, s, o);

    float inv = __frcp_rn(s);
    A0.x *= inv; A0.y *= inv; A0.z *= inv; A0.w *= inv;
    A1.x *= inv; A1.y *= inv; A1.z *= inv; A1.w *= inv;
    L0.x *= inv; L0.y *= inv; L0.z *= inv; L0.w *= inv;
    L1.x *= inv; L1.y *= inv; L1.z *= inv; L1.w *= inv;

    __stcs(orow + 2 * lane,              L0);
    __stcs(orow + 2 * lane + 1,          L1);
    __stcs(orow + 2 * (32 + lane),       A0);
    __stcs(orow + 2 * (32 + lane) + 1,   A1);
}

// ---------------------------------------------------------------------------
// Launch graph:
//   main: cvtW -> gemmA(evA) -> gemmB(evB)
//   side: zero -> count -> alloc -> fill -> [wait evA] agg0 -> [wait evB]
//         agg1+softmax -> (join main)
// gemmA is the 4th submitted launch (ncu slot).
// ---------------------------------------------------------------------------
extern "C" void kernel_launch(void* const* d_in, const int* in_sizes, int n_in,
                              void* d_out, int out_size) {
    const float* onehot = (const float*)d_in[0];
    const int*   ei     = (const int*)d_in[1];    // [2, E]: src then dst
    const float* W      = (const float*)d_in[2];
    const float* b      = (const float*)d_in[3];
    float* out = (float*)d_out;

    static cudaStream_t side = nullptr;
    static cudaEvent_t evFork = nullptr, evA = nullptr, evB = nullptr, evJoin = nullptr;
    if (!side) {
        cudaStreamCreateWithFlags(&side, cudaStreamNonBlocking);
        cudaEventCreateWithFlags(&evFork, cudaEventDisableTiming);
        cudaEventCreateWithFlags(&evA, cudaEventDisableTiming);
        cudaEventCreateWithFlags(&evB, cudaEventDisableTiming);
        cudaEventCreateWithFlags(&evJoin, cudaEventDisableTiming);
        cudaFuncSetAttribute(gemm_kernel, cudaFuncAttributeMaxDynamicSharedMemorySize, SMEM_DYN);
    }

    cudaEventRecord(evFork, 0);
    cudaStreamWaitEvent(side, evFork, 0);

    cvtW_kernel<<<(N_FEAT * N_FEAT / 8 + 255) / 256, 256>>>(W);                     // #1
    zero_kernel<<<(N_NODES + 255) / 256, 256, 0, side>>>();                         // #2
    count_deg_kernel<<<(N_EDGES + 255) / 256, 256, 0, side>>>(ei + N_EDGES);        // #3
    gemm_kernel<<<dim3(2, (N_NODES + BM - 1) / BM), 256, SMEM_DYN>>>(onehot, 0);    // #4 (ncu)
    cudaEventRecord(evA, 0);
    gemm_kernel<<<dim3(2, (N_NODES + BM - 1) / BM), 256, SMEM_DYN>>>(onehot, 1);
    cudaEventRecord(evB, 0);

    alloc_kernel<<<(N_NODES + 255) / 256, 256, 0, side>>>();
    fill_kernel<<<(N_EDGES + 255) / 256, 256, 0, side>>>(ei);

    cudaStreamWaitEvent(side, evA, 0);
    aggregate_half0_kernel<<<(N_NODES + 7) / 8, 256, 0, side>>>(b, out);
    cudaStreamWaitEvent(side, evB, 0);
    aggregate_half1_final_kernel<<<(N_NODES + 7) / 8, 256, 0, side>>>(b, out);

    cudaEventRecord(evJoin, side);
    cudaStreamWaitEvent(0, evJoin, 0);
}